// round 2
// baseline (speedup 1.0000x reference)
#include <cuda_runtime.h>
#include <cuda_bf16.h>
#include <math.h>

// Problem constants (fixed-shape problem)
#define NNODES 50000
#define NEDGES 800000
#define FIN    256
#define HID    256
#define NCLS   32
#define SELFW  2.0f

// ---------------- Device scratch (no allocations allowed) ----------------
__device__ int   g_deg[NNODES];
__device__ int   g_cur[NNODES];
__device__ int   g_off[NNODES + 1];
__device__ int   g_csr_src[NEDGES];
__device__ float g_csr_w[NEDGES];
__device__ float g_dinv[NNODES];
__device__ float g_selfn[NNODES];
__device__ float g_bufA[NNODES * HID];   // GEMM output y
__device__ float g_bufB[NNODES * HID];   // aggregated/activated features

// Compile-time buffer selection so kernel_launch contains ONLY kernel launches.
template <int ID>
__device__ __forceinline__ float* buf_ptr() {
    if (ID == 0) return g_bufA;
    return g_bufB;
}

// ---------------- Precompute: degree, norm, CSR ----------------
__global__ void k_zero_counts() {
    int i = blockIdx.x * blockDim.x + threadIdx.x;
    if (i < NNODES) { g_deg[i] = 0; g_cur[i] = 0; }
}

__global__ void k_hist(const int* __restrict__ dst) {
    int e = blockIdx.x * blockDim.x + threadIdx.x;
    if (e < NEDGES) atomicAdd(&g_deg[dst[e]], 1);
}

__global__ void k_dinv() {
    int i = blockIdx.x * blockDim.x + threadIdx.x;
    if (i < NNODES) {
        float d  = (float)g_deg[i] + SELFW;
        float di = rsqrtf(d);
        g_dinv[i]  = di;
        g_selfn[i] = SELFW * di * di;
    }
}

// Single-block exclusive scan of g_deg -> g_off (chunks of 1024)
__global__ void k_scan() {
    __shared__ int warp_sums[32];
    __shared__ int s_carry;
    const int tid  = threadIdx.x;
    const int lane = tid & 31;
    const int wid  = tid >> 5;
    if (tid == 0) s_carry = 0;
    __syncthreads();
    for (int base = 0; base < NNODES; base += 1024) {
        int i = base + tid;
        int v = (i < NNODES) ? g_deg[i] : 0;
        int x = v;
        #pragma unroll
        for (int o = 1; o < 32; o <<= 1) {
            int y = __shfl_up_sync(0xffffffffu, x, o);
            if (lane >= o) x += y;
        }
        if (lane == 31) warp_sums[wid] = x;
        __syncthreads();
        if (wid == 0) {
            int s = warp_sums[lane];
            #pragma unroll
            for (int o = 1; o < 32; o <<= 1) {
                int y = __shfl_up_sync(0xffffffffu, s, o);
                if (lane >= o) s += y;
            }
            warp_sums[lane] = s;
        }
        __syncthreads();
        int warp_prefix = (wid == 0) ? 0 : warp_sums[wid - 1];
        int incl = x + warp_prefix;
        if (i < NNODES) g_off[i] = s_carry + (incl - v);
        int block_total = warp_sums[31];
        __syncthreads();
        if (tid == 0) s_carry += block_total;
        __syncthreads();
    }
    if (tid == 0) g_off[NNODES] = s_carry;
}

__global__ void k_fill_csr(const int* __restrict__ src, const int* __restrict__ dst) {
    int e = blockIdx.x * blockDim.x + threadIdx.x;
    if (e < NEDGES) {
        int s = src[e], d = dst[e];
        int p = atomicAdd(&g_cur[d], 1);
        int idx = g_off[d] + p;
        g_csr_src[idx] = s;
        g_csr_w[idx]   = g_dinv[s] * g_dinv[d];
    }
}

// ---------------- SGEMM: C[Nrows,Mcols] = A[Nrows,K] @ B[K,Mcols] ----------------
// SRC: -1 = external pointer A, 0 = g_bufA, 1 = g_bufB. DSTID: 0 = g_bufA, 1 = g_bufB.
template <int BM, int BN, int BK, int TM, int TN, int SRC, int DSTID>
__global__ void sgemm_kernel(int Nrows, int K, int Mcols,
                             const float* __restrict__ Aext,
                             const float* __restrict__ B) {
    const float* __restrict__ A = (SRC < 0) ? Aext : buf_ptr<SRC>();
    float* __restrict__ C = buf_ptr<DSTID>();

    constexpr int THREADS = (BM / TM) * (BN / TN);
    __shared__ float As[BK][BM];
    __shared__ float Bs[BK][BN];

    const int tid  = threadIdx.x;
    const int tcol = tid % (BN / TN);
    const int trow = tid / (BN / TN);
    const int row0 = blockIdx.y * BM;
    const int col0 = blockIdx.x * BN;

    constexpr int AF4     = BK / 4;
    constexpr int ASTRIDE = THREADS / AF4;
    constexpr int AITERS  = BM / ASTRIDE;
    const int a_row0 = tid / AF4;
    const int a_k4   = (tid % AF4) * 4;

    constexpr int BF4     = BN / 4;
    constexpr int BSTRIDE = THREADS / BF4;
    constexpr int BITERS  = BK / BSTRIDE;
    const int b_k0 = tid / BF4;
    const int b_n4 = (tid % BF4) * 4;

    float acc[TM][TN] = {};

    for (int k0 = 0; k0 < K; k0 += BK) {
        #pragma unroll
        for (int it = 0; it < AITERS; it++) {
            int r = a_row0 + it * ASTRIDE;
            int g = row0 + r;
            float4 v = make_float4(0.f, 0.f, 0.f, 0.f);
            if (g < Nrows)
                v = *reinterpret_cast<const float4*>(&A[(long)g * K + k0 + a_k4]);
            As[a_k4 + 0][r] = v.x;
            As[a_k4 + 1][r] = v.y;
            As[a_k4 + 2][r] = v.z;
            As[a_k4 + 3][r] = v.w;
        }
        #pragma unroll
        for (int it = 0; it < BITERS; it++) {
            int r = b_k0 + it * BSTRIDE;
            *reinterpret_cast<float4*>(&Bs[r][b_n4]) =
                *reinterpret_cast<const float4*>(&B[(long)(k0 + r) * Mcols + col0 + b_n4]);
        }
        __syncthreads();
        #pragma unroll
        for (int k = 0; k < BK; k++) {
            float ra[TM], rb[TN];
            #pragma unroll
            for (int i = 0; i < TM; i++) ra[i] = As[k][trow * TM + i];
            #pragma unroll
            for (int j = 0; j < TN; j++) rb[j] = Bs[k][tcol * TN + j];
            #pragma unroll
            for (int i = 0; i < TM; i++)
                #pragma unroll
                for (int j = 0; j < TN; j++)
                    acc[i][j] = fmaf(ra[i], rb[j], acc[i][j]);
        }
        __syncthreads();
    }
    #pragma unroll
    for (int i = 0; i < TM; i++) {
        int g = row0 + trow * TM + i;
        if (g >= Nrows) continue;
        #pragma unroll
        for (int j = 0; j < TN; j += 4) {
            float4 v;
            v.x = acc[i][j]; v.y = acc[i][j + 1]; v.z = acc[i][j + 2]; v.w = acc[i][j + 3];
            *reinterpret_cast<float4*>(&C[(long)g * Mcols + col0 + tcol * TN + j]) = v;
        }
    }
}

// ---------------- Aggregate: out[i] = act( sum_nbr w*y[src] + selfn[i]*y[i] + b ) ----------
// OUTACT: 1 = relu, 2 = tanh. SRCID: 0/1 = g_bufA/g_bufB. DSTID: 0/1 = bufs, -1 = external out.
template <int MC, int OUTACT, int SRCID, int DSTID>
__global__ void aggregate_kernel(const float* __restrict__ bias,
                                 float* __restrict__ ext_out) {
    const float* __restrict__ y = buf_ptr<SRCID>();
    float* __restrict__ outp = (DSTID < 0) ? ext_out : buf_ptr<DSTID>();

    constexpr int TPN = MC / 4;      // threads per node (float4 each)
    constexpr int NPB = 256 / TPN;   // nodes per block
    int node = blockIdx.x * NPB + threadIdx.x / TPN;
    if (node >= NNODES) return;
    int t = threadIdx.x % TPN;

    const float4* __restrict__ yv = reinterpret_cast<const float4*>(y);
    float4 self = yv[(long)node * TPN + t];
    float  sn   = g_selfn[node];
    float4 bv   = reinterpret_cast<const float4*>(bias)[t];

    float4 acc;
    acc.x = fmaf(sn, self.x, bv.x);
    acc.y = fmaf(sn, self.y, bv.y);
    acc.z = fmaf(sn, self.z, bv.z);
    acc.w = fmaf(sn, self.w, bv.w);

    int beg = g_off[node], end = g_off[node + 1];
    for (int j = beg; j < end; j++) {
        int   s = __ldg(&g_csr_src[j]);
        float w = __ldg(&g_csr_w[j]);
        float4 v = yv[(long)s * TPN + t];
        acc.x = fmaf(w, v.x, acc.x);
        acc.y = fmaf(w, v.y, acc.y);
        acc.z = fmaf(w, v.z, acc.z);
        acc.w = fmaf(w, v.w, acc.w);
    }
    if (OUTACT == 1) {
        acc.x = fmaxf(acc.x, 0.f); acc.y = fmaxf(acc.y, 0.f);
        acc.z = fmaxf(acc.z, 0.f); acc.w = fmaxf(acc.w, 0.f);
    } else {
        acc.x = tanhf(acc.x); acc.y = tanhf(acc.y);
        acc.z = tanhf(acc.z); acc.w = tanhf(acc.w);
    }
    reinterpret_cast<float4*>(outp)[(long)node * TPN + t] = acc;
}

// ---------------- Launch ----------------
extern "C" void kernel_launch(void* const* d_in, const int* in_sizes, int n_in,
                              void* d_out, int out_size) {
    const float* x     = (const float*)d_in[0];
    const int*   ei    = (const int*)d_in[1];
    const float* W_in  = (const float*)d_in[2];
    const float* b_in  = (const float*)d_in[3];
    const float* W_h   = (const float*)d_in[4];
    const float* b_h   = (const float*)d_in[5];
    const float* W_out = (const float*)d_in[6];
    const float* b_out = (const float*)d_in[7];
    float* out = (float*)d_out;

    const int* src = ei;
    const int* dst = ei + NEDGES;

    const int nthreads = 256;
    const int nblk_nodes = (NNODES + nthreads - 1) / nthreads;
    const int nblk_edges = (NEDGES + nthreads - 1) / nthreads;

    // ---- preprocessing: degree -> dinv/self_norm -> offsets -> CSR ----
    k_zero_counts<<<nblk_nodes, nthreads>>>();
    k_hist<<<nblk_edges, nthreads>>>(dst);
    k_dinv<<<nblk_nodes, nthreads>>>();
    k_scan<<<1, 1024>>>();
    k_fill_csr<<<nblk_edges, nthreads>>>(src, dst);

    // ---- GEMM configs ----
    dim3 gemmH_grid(HID / 128, (NNODES + 127) / 128);   // 256-wide output
    dim3 gemmO_grid(NCLS / 32, (NNODES + 127) / 128);   // 32-wide output

    const int agg256_blocks = (NNODES + 3) / 4;      // 4 nodes/block (64 thr/node)
    const int agg32_blocks  = (NNODES + 31) / 32;    // 32 nodes/block (8 thr/node)

    // Layer 0: x @ W_in -> bufA ; aggregate+relu -> bufB
    sgemm_kernel<128, 128, 16, 8, 8, -1, 0><<<gemmH_grid, 256>>>(NNODES, FIN, HID, x, W_in);
    aggregate_kernel<HID, 1, 0, 1><<<agg256_blocks, 256>>>(b_in, nullptr);

    // Hidden layer 0: bufB @ W -> bufA ; aggregate+relu -> bufB
    sgemm_kernel<128, 128, 16, 8, 8, 1, 0><<<gemmH_grid, 256>>>(NNODES, HID, HID, nullptr, W_h);
    aggregate_kernel<HID, 1, 0, 1><<<agg256_blocks, 256>>>(b_h, nullptr);

    // Hidden layer 1
    sgemm_kernel<128, 128, 16, 8, 8, 1, 0><<<gemmH_grid, 256>>>(NNODES, HID, HID, nullptr,
                                                                W_h + (long)HID * HID);
    aggregate_kernel<HID, 1, 0, 1><<<agg256_blocks, 256>>>(b_h + HID, nullptr);

    // Output layer: bufB @ W_out -> bufA(first N*32) ; aggregate+tanh -> d_out
    sgemm_kernel<128, 32, 16, 8, 4, 1, 0><<<gemmO_grid, 128>>>(NNODES, HID, NCLS, nullptr, W_out);
    aggregate_kernel<NCLS, 2, 0, -1><<<agg32_blocks, 256>>>(b_out, out);

    (void)in_sizes; (void)n_in; (void)out_size;
}

// round 3
// speedup vs baseline: 1.7072x; 1.7072x over previous
#include <cuda_runtime.h>
#include <cuda_bf16.h>
#include <math.h>
#include <stdint.h>

// Problem constants (fixed-shape problem)
#define NNODES 50000
#define NEDGES 800000
#define FIN    256
#define HID    256
#define NCLS   32
#define SELFW  2.0f

#define NB512  98            // ceil(50000/512)
#define WSZ_TOT (3*256*256 + 256*32)   // all weights, bf16 split storage

// ---------------- Device scratch (no allocations allowed) ----------------
__device__ int   g_deg[NNODES];
__device__ int   g_cur[NNODES];
__device__ int   g_off[NNODES + 1];
__device__ int   g_blksum[NB512];
__device__ int   g_blkoff[NB512];
__device__ int   g_csr_src[NEDGES];
__device__ float g_csr_w[NEDGES];
__device__ float g_dinv[NNODES];
__device__ float g_selfn[NNODES];
__device__ float g_y[NNODES * HID];                    // GEMM output (fp32)
__device__ __nv_bfloat16 g_Ahi[NNODES * HID];          // activation hi split
__device__ __nv_bfloat16 g_Alo[NNODES * HID];          // activation lo split
__device__ __nv_bfloat16 g_Whi[WSZ_TOT];               // weight hi split
__device__ __nv_bfloat16 g_Wlo[WSZ_TOT];               // weight lo split

// ---------------- small helpers ----------------
__device__ __forceinline__ uint32_t sptr(const void* p) {
    return (uint32_t)__cvta_generic_to_shared(p);
}
__device__ __forceinline__ void ldsm_x4(uint32_t& r0, uint32_t& r1, uint32_t& r2, uint32_t& r3,
                                        uint32_t addr) {
    asm volatile("ldmatrix.sync.aligned.m8n8.x4.shared.b16 {%0,%1,%2,%3}, [%4];\n"
                 : "=r"(r0), "=r"(r1), "=r"(r2), "=r"(r3) : "r"(addr));
}
__device__ __forceinline__ void ldsm_x4_t(uint32_t& r0, uint32_t& r1, uint32_t& r2, uint32_t& r3,
                                          uint32_t addr) {
    asm volatile("ldmatrix.sync.aligned.m8n8.x4.trans.shared.b16 {%0,%1,%2,%3}, [%4];\n"
                 : "=r"(r0), "=r"(r1), "=r"(r2), "=r"(r3) : "r"(addr));
}
__device__ __forceinline__ void mma_bf16(float& c0, float& c1, float& c2, float& c3,
                                         uint32_t a0, uint32_t a1, uint32_t a2, uint32_t a3,
                                         uint32_t b0, uint32_t b1) {
    asm volatile("mma.sync.aligned.m16n8k16.row.col.f32.bf16.bf16.f32 "
                 "{%0,%1,%2,%3}, {%4,%5,%6,%7}, {%8,%9}, {%0,%1,%2,%3};\n"
                 : "+f"(c0), "+f"(c1), "+f"(c2), "+f"(c3)
                 : "r"(a0), "r"(a1), "r"(a2), "r"(a3), "r"(b0), "r"(b1));
}

// ---------------- Precompute: degree, norm, CSR ----------------
__global__ void k_zero_counts() {
    int i = blockIdx.x * blockDim.x + threadIdx.x;
    if (i < NNODES) { g_deg[i] = 0; g_cur[i] = 0; }
}

__global__ void k_hist(const int* __restrict__ dst) {
    int e = blockIdx.x * blockDim.x + threadIdx.x;
    if (e < NEDGES) atomicAdd(&g_deg[dst[e]], 1);
}

__global__ void k_dinv() {
    int i = blockIdx.x * blockDim.x + threadIdx.x;
    if (i < NNODES) {
        float d  = (float)g_deg[i] + SELFW;
        float di = rsqrtf(d);
        g_dinv[i]  = di;
        g_selfn[i] = SELFW * di * di;
    }
}

// ---- 3-phase scan: block sums -> scan sums -> apply ----
__global__ void k_blksum() {
    __shared__ int wsum[16];
    int b = blockIdx.x, tid = threadIdx.x;
    int i = b * 512 + tid;
    int v = (i < NNODES) ? g_deg[i] : 0;
    #pragma unroll
    for (int o = 16; o > 0; o >>= 1) v += __shfl_down_sync(0xffffffffu, v, o);
    if ((tid & 31) == 0) wsum[tid >> 5] = v;
    __syncthreads();
    if (tid < 16) {
        int s = wsum[tid];
        #pragma unroll
        for (int o = 8; o > 0; o >>= 1) s += __shfl_down_sync(0xffffu, s, o);
        if (tid == 0) g_blksum[b] = s;
    }
}

__global__ void k_blkscan() {   // 1 block, 128 threads, scans NB512 (=98) sums
    __shared__ int wtot[4];
    int tid = threadIdx.x, lane = tid & 31, wid = tid >> 5;
    int v = (tid < NB512) ? g_blksum[tid] : 0;
    int x = v;
    #pragma unroll
    for (int o = 1; o < 32; o <<= 1) {
        int y = __shfl_up_sync(0xffffffffu, x, o);
        if (lane >= o) x += y;
    }
    if (lane == 31) wtot[wid] = x;
    __syncthreads();
    int woff = 0;
    for (int w = 0; w < wid; w++) woff += wtot[w];
    int incl = x + woff;
    if (tid < NB512) g_blkoff[tid] = incl - v;       // exclusive
    if (tid == NB512 - 1) g_off[NNODES] = incl;      // grand total
}

__global__ void k_scanfinal() {
    __shared__ int wsum[16];
    int b = blockIdx.x, tid = threadIdx.x, lane = tid & 31, wid = tid >> 5;
    int i = b * 512 + tid;
    int v = (i < NNODES) ? g_deg[i] : 0;
    int x = v;
    #pragma unroll
    for (int o = 1; o < 32; o <<= 1) {
        int y = __shfl_up_sync(0xffffffffu, x, o);
        if (lane >= o) x += y;
    }
    if (lane == 31) wsum[wid] = x;
    __syncthreads();
    if (wid == 0) {
        int s = (lane < 16) ? wsum[lane] : 0;
        #pragma unroll
        for (int o = 1; o < 16; o <<= 1) {
            int y = __shfl_up_sync(0xffffffffu, s, o);
            if (lane >= o) s += y;
        }
        if (lane < 16) wsum[lane] = s;
    }
    __syncthreads();
    int woff = (wid == 0) ? 0 : wsum[wid - 1];
    if (i < NNODES) g_off[i] = g_blkoff[b] + woff + (x - v);
}

__global__ void k_fill_csr(const int* __restrict__ src, const int* __restrict__ dst) {
    int e = blockIdx.x * blockDim.x + threadIdx.x;
    if (e < NEDGES) {
        int s = src[e], d = dst[e];
        int p = atomicAdd(&g_cur[d], 1);
        int idx = g_off[d] + p;
        g_csr_src[idx] = s;
        g_csr_w[idx]   = g_dinv[s] * g_dinv[d];
    }
}

// ---------------- fp32 -> bf16 hi/lo split conversions ----------------
__device__ __forceinline__ void split2(float a, float b, __nv_bfloat162& h2, __nv_bfloat162& l2) {
    __nv_bfloat16 ha = __float2bfloat16_rn(a);
    __nv_bfloat16 hb = __float2bfloat16_rn(b);
    __nv_bfloat16 la = __float2bfloat16_rn(a - __bfloat162float(ha));
    __nv_bfloat16 lb = __float2bfloat16_rn(b - __bfloat162float(hb));
    h2 = __nv_bfloat162(ha, hb);
    l2 = __nv_bfloat162(la, lb);
}

__global__ void k_split_x(const float* __restrict__ src, int n) {
    int i = blockIdx.x * blockDim.x + threadIdx.x;
    if (i * 4 >= n) return;
    float4 v = reinterpret_cast<const float4*>(src)[i];
    __nv_bfloat162 h0, l0, h1, l1;
    split2(v.x, v.y, h0, l0);
    split2(v.z, v.w, h1, l1);
    __nv_bfloat162* H = reinterpret_cast<__nv_bfloat162*>(g_Ahi);
    __nv_bfloat162* L = reinterpret_cast<__nv_bfloat162*>(g_Alo);
    H[i * 2] = h0; H[i * 2 + 1] = h1;
    L[i * 2] = l0; L[i * 2 + 1] = l1;
}

__global__ void k_split_w(const float* __restrict__ src, int woff, int n) {
    int i = blockIdx.x * blockDim.x + threadIdx.x;
    if (i * 4 >= n) return;
    float4 v = reinterpret_cast<const float4*>(src)[i];
    __nv_bfloat162 h0, l0, h1, l1;
    split2(v.x, v.y, h0, l0);
    split2(v.z, v.w, h1, l1);
    __nv_bfloat162* H = reinterpret_cast<__nv_bfloat162*>(g_Whi + woff);
    __nv_bfloat162* L = reinterpret_cast<__nv_bfloat162*>(g_Wlo + woff);
    H[i * 2] = h0; H[i * 2 + 1] = h1;
    L[i * 2] = l0; L[i * 2 + 1] = l1;
}

// ---------------- Tensor-core split GEMM ----------------
// C[Nrows, Mcols] = A[Nrows, K] @ W[K, Mcols], A = Ahi+Alo, W = Whi+Wlo (bf16 splits)
// 3-term: hi*hi + hi*lo + lo*hi, fp32 accumulate. A from g_Ahi/g_Alo, W from g_Whi/g_Wlo+woff,
// C into g_y.
template <int BM, int BN, int WM, int WN>
__global__ void mma_gemm(int Nrows, int K, int Mcols, int woff) {
    constexpr int WARPS_M = BM / WM;
    constexpr int WARPS_N = BN / WN;
    constexpr int THREADS = WARPS_M * WARPS_N * 32;
    constexpr int FM = WM / 16;
    constexpr int FN = WN / 8;
    constexpr int BK = 32;
    constexpr int APAD = 8;   // A row stride 40 bf16 = 80B (16B-aligned, conflict-free)
    constexpr int BPAD = 8;   // B row stride BN+8

    __shared__ __nv_bfloat16 As[2][BM][BK + APAD];
    __shared__ __nv_bfloat16 Bs[2][BK][BN + BPAD];

    const int tid  = threadIdx.x;
    const int lane = tid & 31;
    const int w    = tid >> 5;
    const int wm0  = (w / WARPS_N) * WM;
    const int wn0  = (w % WARPS_N) * WN;
    const int row0 = blockIdx.y * BM;
    const int col0 = blockIdx.x * BN;

    const __nv_bfloat16* __restrict__ Whi = g_Whi + woff;
    const __nv_bfloat16* __restrict__ Wlo = g_Wlo + woff;

    float acc[FM][FN][4];
    #pragma unroll
    for (int i = 0; i < FM; i++)
        #pragma unroll
        for (int j = 0; j < FN; j++)
            #pragma unroll
            for (int r = 0; r < 4; r++) acc[i][j][r] = 0.f;

    constexpr int AVECS = BM * BK / 8;        // uint4 (8 bf16) loads
    constexpr int AITER = AVECS / THREADS;
    constexpr int BVECS = BK * BN / 8;
    constexpr int BITER = BVECS / THREADS;

    #pragma unroll 1
    for (int k0 = 0; k0 < K; k0 += BK) {
        // load A tile (hi+lo)
        #pragma unroll
        for (int it = 0; it < AITER; it++) {
            int v = tid + it * THREADS;
            int r = v / (BK / 8);
            int q = v % (BK / 8);
            int grow = row0 + r;
            uint4 vh = make_uint4(0, 0, 0, 0), vl = make_uint4(0, 0, 0, 0);
            if (grow < Nrows) {
                long gofs = (long)grow * K + k0 + q * 8;
                vh = *reinterpret_cast<const uint4*>(&g_Ahi[gofs]);
                vl = *reinterpret_cast<const uint4*>(&g_Alo[gofs]);
            }
            *reinterpret_cast<uint4*>(&As[0][r][q * 8]) = vh;
            *reinterpret_cast<uint4*>(&As[1][r][q * 8]) = vl;
        }
        // load B tile (hi+lo)
        #pragma unroll
        for (int it = 0; it < BITER; it++) {
            int v = tid + it * THREADS;
            int r = v / (BN / 8);
            int q = v % (BN / 8);
            long gofs = (long)(k0 + r) * Mcols + col0 + q * 8;
            *reinterpret_cast<uint4*>(&Bs[0][r][q * 8]) =
                *reinterpret_cast<const uint4*>(&Whi[gofs]);
            *reinterpret_cast<uint4*>(&Bs[1][r][q * 8]) =
                *reinterpret_cast<const uint4*>(&Wlo[gofs]);
        }
        __syncthreads();

        #pragma unroll
        for (int k16 = 0; k16 < BK / 16; k16++) {
            uint32_t ah[FM][4], al[FM][4], bh[FN][2], bl[FN][2];
            const int arow = lane & 15;
            const int acol = k16 * 16 + ((lane >> 4) << 3);
            #pragma unroll
            for (int fm = 0; fm < FM; fm++) {
                ldsm_x4(ah[fm][0], ah[fm][1], ah[fm][2], ah[fm][3],
                        sptr(&As[0][wm0 + fm * 16 + arow][acol]));
                ldsm_x4(al[fm][0], al[fm][1], al[fm][2], al[fm][3],
                        sptr(&As[1][wm0 + fm * 16 + arow][acol]));
            }
            const int brow = k16 * 16 + (lane & 15);
            const int bcofs = (lane >> 4) << 3;
            #pragma unroll
            for (int p = 0; p < FN / 2; p++) {
                ldsm_x4_t(bh[p * 2][0], bh[p * 2][1], bh[p * 2 + 1][0], bh[p * 2 + 1][1],
                          sptr(&Bs[0][brow][wn0 + p * 16 + bcofs]));
                ldsm_x4_t(bl[p * 2][0], bl[p * 2][1], bl[p * 2 + 1][0], bl[p * 2 + 1][1],
                          sptr(&Bs[1][brow][wn0 + p * 16 + bcofs]));
            }
            #pragma unroll
            for (int fm = 0; fm < FM; fm++)
                #pragma unroll
                for (int fn = 0; fn < FN; fn++) {
                    float* c = acc[fm][fn];
                    mma_bf16(c[0], c[1], c[2], c[3],
                             ah[fm][0], ah[fm][1], ah[fm][2], ah[fm][3],
                             bh[fn][0], bh[fn][1]);
                    mma_bf16(c[0], c[1], c[2], c[3],
                             ah[fm][0], ah[fm][1], ah[fm][2], ah[fm][3],
                             bl[fn][0], bl[fn][1]);
                    mma_bf16(c[0], c[1], c[2], c[3],
                             al[fm][0], al[fm][1], al[fm][2], al[fm][3],
                             bh[fn][0], bh[fn][1]);
                }
        }
        __syncthreads();
    }

    // epilogue -> g_y
    #pragma unroll
    for (int fm = 0; fm < FM; fm++) {
        int grow0 = row0 + wm0 + fm * 16 + (lane >> 2);
        #pragma unroll
        for (int fn = 0; fn < FN; fn++) {
            int gcol = col0 + wn0 + fn * 8 + (lane & 3) * 2;
            float* c = acc[fm][fn];
            if (grow0 < Nrows)
                *reinterpret_cast<float2*>(&g_y[(long)grow0 * Mcols + gcol]) =
                    make_float2(c[0], c[1]);
            if (grow0 + 8 < Nrows)
                *reinterpret_cast<float2*>(&g_y[(long)(grow0 + 8) * Mcols + gcol]) =
                    make_float2(c[2], c[3]);
        }
    }
}

// ---------------- Aggregate: out[i] = act( sum_nbr w*y[src] + selfn[i]*y[i] + b ) ----------
// DSTMODE 0: relu, write bf16 hi/lo split into g_Ahi/g_Alo
// DSTMODE 1: tanh, write fp32 to ext_out
template <int MC, int DSTMODE>
__global__ void aggregate_kernel(const float* __restrict__ bias,
                                 float* __restrict__ ext_out) {
    constexpr int TPN = MC / 4;      // threads per node (float4 each)
    constexpr int NPB = 256 / TPN;   // nodes per block
    int node = blockIdx.x * NPB + threadIdx.x / TPN;
    if (node >= NNODES) return;
    int t = threadIdx.x % TPN;

    const float4* __restrict__ yv = reinterpret_cast<const float4*>(g_y);
    float4 self = yv[(long)node * TPN + t];
    float  sn   = g_selfn[node];
    float4 bv   = reinterpret_cast<const float4*>(bias)[t];

    float4 acc;
    acc.x = fmaf(sn, self.x, bv.x);
    acc.y = fmaf(sn, self.y, bv.y);
    acc.z = fmaf(sn, self.z, bv.z);
    acc.w = fmaf(sn, self.w, bv.w);

    int beg = g_off[node], end = g_off[node + 1];
    for (int j = beg; j < end; j++) {
        int   s = __ldg(&g_csr_src[j]);
        float w = __ldg(&g_csr_w[j]);
        float4 v = yv[(long)s * TPN + t];
        acc.x = fmaf(w, v.x, acc.x);
        acc.y = fmaf(w, v.y, acc.y);
        acc.z = fmaf(w, v.z, acc.z);
        acc.w = fmaf(w, v.w, acc.w);
    }
    if (DSTMODE == 0) {
        acc.x = fmaxf(acc.x, 0.f); acc.y = fmaxf(acc.y, 0.f);
        acc.z = fmaxf(acc.z, 0.f); acc.w = fmaxf(acc.w, 0.f);
        __nv_bfloat162 h0, l0, h1, l1;
        split2(acc.x, acc.y, h0, l0);
        split2(acc.z, acc.w, h1, l1);
        long base = (long)node * TPN + t;   // float4 granularity index
        __nv_bfloat162* H = reinterpret_cast<__nv_bfloat162*>(g_Ahi);
        __nv_bfloat162* L = reinterpret_cast<__nv_bfloat162*>(g_Alo);
        H[base * 2] = h0; H[base * 2 + 1] = h1;
        L[base * 2] = l0; L[base * 2 + 1] = l1;
    } else {
        acc.x = tanhf(acc.x); acc.y = tanhf(acc.y);
        acc.z = tanhf(acc.z); acc.w = tanhf(acc.w);
        reinterpret_cast<float4*>(ext_out)[(long)node * TPN + t] = acc;
    }
}

// ---------------- Launch ----------------
extern "C" void kernel_launch(void* const* d_in, const int* in_sizes, int n_in,
                              void* d_out, int out_size) {
    const float* x     = (const float*)d_in[0];
    const int*   ei    = (const int*)d_in[1];
    const float* W_in  = (const float*)d_in[2];
    const float* b_in  = (const float*)d_in[3];
    const float* W_h   = (const float*)d_in[4];
    const float* b_h   = (const float*)d_in[5];
    const float* W_out = (const float*)d_in[6];
    const float* b_out = (const float*)d_in[7];
    float* out = (float*)d_out;

    const int* src = ei;
    const int* dst = ei + NEDGES;

    const int nthreads = 256;
    const int nblk_nodes = (NNODES + nthreads - 1) / nthreads;
    const int nblk_edges = (NEDGES + nthreads - 1) / nthreads;

    // ---- preprocessing: degree -> dinv/self_norm -> offsets -> CSR ----
    k_zero_counts<<<nblk_nodes, nthreads>>>();
    k_hist<<<nblk_edges, nthreads>>>(dst);
    k_dinv<<<nblk_nodes, nthreads>>>();
    k_blksum<<<NB512, 512>>>();
    k_blkscan<<<1, 128>>>();
    k_scanfinal<<<NB512, 512>>>();
    k_fill_csr<<<nblk_edges, nthreads>>>(src, dst);

    // ---- weight + input splits ----
    k_split_w<<<(256 * 256 / 4 + 255) / 256, 256>>>(W_in, 0, 256 * 256);
    k_split_w<<<(2 * 256 * 256 / 4 + 255) / 256, 256>>>(W_h, 256 * 256, 2 * 256 * 256);
    k_split_w<<<(256 * 32 / 4 + 255) / 256, 256>>>(W_out, 3 * 256 * 256, 256 * 32);
    k_split_x<<<(NNODES * FIN / 4 + 255) / 256, 256>>>(x, NNODES * FIN);

    // ---- GEMM configs ----
    dim3 gemmH_grid(HID / 128, (NNODES + 127) / 128);   // BM=128, BN=128, 256 thr
    dim3 gemmO_grid(1, (NNODES + 127) / 128);           // BM=128, BN=32, 128 thr

    const int agg256_blocks = (NNODES + 3) / 4;
    const int agg32_blocks  = (NNODES + 31) / 32;

    // Layer 0
    mma_gemm<128, 128, 64, 32><<<gemmH_grid, 256>>>(NNODES, FIN, HID, 0);
    aggregate_kernel<HID, 0><<<agg256_blocks, 256>>>(b_in, nullptr);
    // Hidden layer 0
    mma_gemm<128, 128, 64, 32><<<gemmH_grid, 256>>>(NNODES, HID, HID, 256 * 256);
    aggregate_kernel<HID, 0><<<agg256_blocks, 256>>>(b_h, nullptr);
    // Hidden layer 1
    mma_gemm<128, 128, 64, 32><<<gemmH_grid, 256>>>(NNODES, HID, HID, 2 * 256 * 256);
    aggregate_kernel<HID, 0><<<agg256_blocks, 256>>>(b_h + HID, nullptr);
    // Output layer
    mma_gemm<128, 32, 32, 32><<<gemmO_grid, 128>>>(NNODES, HID, NCLS, 3 * 256 * 256);
    aggregate_kernel<NCLS, 1><<<agg32_blocks, 256>>>(b_out, out);

    (void)in_sizes; (void)n_in; (void)out_size;
}